// round 1
// baseline (speedup 1.0000x reference)
#include <cuda_runtime.h>

// Haar DWT2: x[8,64,512,512] f32 -> (ll, lh, hl, hh) each [8,64,256,256],
// concatenated into d_out in that order.
//
// Layout constants (fixed problem shape):
//   B*C      = 512 planes
//   in plane = 512*512 = 262144 elems
//   out plane= 256*256 = 65536 elems
//   subband stride = 512*65536 = 33554432 elems

#define IN_W      512
#define OUT_W     256
#define OUT_H     256
#define IN_PLANE  (512*512)
#define OUT_PLANE (256*256)
#define SUBBAND   (512*256*256)

// Each thread: 4 output cols (8 input cols) at one output row of one plane.
// 64 threads cover one output row. Total threads = 512 * 256 * 64 = 8388608.
__global__ void __launch_bounds__(256) haar_dwt2_kernel(
    const float* __restrict__ x, float* __restrict__ out)
{
    unsigned idx = blockIdx.x * blockDim.x + threadIdx.x;   // < 8388608
    unsigned t   = idx & 63u;          // 0..63  -> output cols [4t, 4t+3]
    unsigned oy  = (idx >> 6) & 255u;  // 0..255 output row
    unsigned bc  = idx >> 14;          // 0..511 plane

    const float* row0 = x + (size_t)bc * IN_PLANE + (size_t)(2u * oy) * IN_W + 8u * t;
    const float* row1 = row0 + IN_W;

    // Front-batch the 4 independent 128-bit loads for MLP.
    float4 r0a = *reinterpret_cast<const float4*>(row0);
    float4 r0b = *reinterpret_cast<const float4*>(row0 + 4);
    float4 r1a = *reinterpret_cast<const float4*>(row1);
    float4 r1b = *reinterpret_cast<const float4*>(row1 + 4);

    // a=row0 even cols, b=row0 odd cols, c=row1 even, d=row1 odd
    // output col j in {0..3}
    float a0 = r0a.x, b0 = r0a.y, a1 = r0a.z, b1 = r0a.w;
    float a2 = r0b.x, b2 = r0b.y, a3 = r0b.z, b3 = r0b.w;
    float c0 = r1a.x, d0 = r1a.y, c1 = r1a.z, d1 = r1a.w;
    float c2 = r1b.x, d2 = r1b.y, c3 = r1b.z, d3 = r1b.w;

    const float S = 0.5f;

    float4 ll, lh, hl, hh;
    {
        float ab = a0 + b0, cd = c0 + d0, amb = a0 - b0, cmd = c0 - d0;
        ll.x = (ab + cd) * S; lh.x = (ab - cd) * S;
        hl.x = (amb + cmd) * S; hh.x = (amb - cmd) * S;
    }
    {
        float ab = a1 + b1, cd = c1 + d1, amb = a1 - b1, cmd = c1 - d1;
        ll.y = (ab + cd) * S; lh.y = (ab - cd) * S;
        hl.y = (amb + cmd) * S; hh.y = (amb - cmd) * S;
    }
    {
        float ab = a2 + b2, cd = c2 + d2, amb = a2 - b2, cmd = c2 - d2;
        ll.z = (ab + cd) * S; lh.z = (ab - cd) * S;
        hl.z = (amb + cmd) * S; hh.z = (amb - cmd) * S;
    }
    {
        float ab = a3 + b3, cd = c3 + d3, amb = a3 - b3, cmd = c3 - d3;
        ll.w = (ab + cd) * S; lh.w = (ab - cd) * S;
        hl.w = (amb + cmd) * S; hh.w = (amb - cmd) * S;
    }

    size_t obase = (size_t)bc * OUT_PLANE + (size_t)oy * OUT_W + 4u * t;
    *reinterpret_cast<float4*>(out + obase)                      = ll;
    *reinterpret_cast<float4*>(out + obase + (size_t)SUBBAND)    = lh;
    *reinterpret_cast<float4*>(out + obase + (size_t)SUBBAND*2)  = hl;
    *reinterpret_cast<float4*>(out + obase + (size_t)SUBBAND*3)  = hh;
}

extern "C" void kernel_launch(void* const* d_in, const int* in_sizes, int n_in,
                              void* d_out, int out_size)
{
    const float* x = (const float*)d_in[0];
    float* out = (float*)d_out;
    // 8388608 threads / 256 = 32768 blocks
    haar_dwt2_kernel<<<32768, 256>>>(x, out);
}

// round 3
// speedup vs baseline: 1.0016x; 1.0016x over previous
#include <cuda_runtime.h>

// Haar DWT2: x[8,64,512,512] f32 -> (ll, lh, hl, hh) each [8,64,256,256],
// concatenated into d_out in that order.

#define IN_W      512
#define OUT_W     256
#define IN_PLANE  (512*512)
#define OUT_PLANE (256*256)
#define SUBBAND   (512*256*256)

// Each thread: 2 output rows x 4 output cols (4 input rows x 8 input cols).
// 64 threads cover one output row pair across the width.
// Total threads = 512 planes * 128 row-pairs * 64 = 4,194,304.
__global__ void __launch_bounds__(256) haar_dwt2_kernel(
    const float* __restrict__ x, float* __restrict__ out)
{
    unsigned idx = blockIdx.x * blockDim.x + threadIdx.x;   // < 4194304
    unsigned t   = idx & 63u;          // 0..63  -> output cols [4t, 4t+3]
    unsigned op  = (idx >> 6) & 127u;  // 0..127 output row pair (rows 2op, 2op+1)
    unsigned bc  = idx >> 13;          // 0..511 plane

    const float* base = x + (size_t)bc * IN_PLANE + (size_t)(4u * op) * IN_W + 8u * t;

    // 8 independent 128-bit streaming loads, front-batched for MLP.
    float4 r0a = __ldcs(reinterpret_cast<const float4*>(base));
    float4 r0b = __ldcs(reinterpret_cast<const float4*>(base + 4));
    float4 r1a = __ldcs(reinterpret_cast<const float4*>(base + IN_W));
    float4 r1b = __ldcs(reinterpret_cast<const float4*>(base + IN_W + 4));
    float4 r2a = __ldcs(reinterpret_cast<const float4*>(base + 2*IN_W));
    float4 r2b = __ldcs(reinterpret_cast<const float4*>(base + 2*IN_W + 4));
    float4 r3a = __ldcs(reinterpret_cast<const float4*>(base + 3*IN_W));
    float4 r3b = __ldcs(reinterpret_cast<const float4*>(base + 3*IN_W + 4));

    const float S = 0.5f;

    size_t obase = (size_t)bc * OUT_PLANE + (size_t)(2u * op) * OUT_W + 4u * t;

    // ---- output row 0 (input rows 0,1) ----
    {
        float4 ll, lh, hl, hh;
        {
            float ab = r0a.x + r0a.y, cd = r1a.x + r1a.y;
            float amb = r0a.x - r0a.y, cmd = r1a.x - r1a.y;
            ll.x = (ab + cd) * S; lh.x = (ab - cd) * S;
            hl.x = (amb + cmd) * S; hh.x = (amb - cmd) * S;
        }
        {
            float ab = r0a.z + r0a.w, cd = r1a.z + r1a.w;
            float amb = r0a.z - r0a.w, cmd = r1a.z - r1a.w;
            ll.y = (ab + cd) * S; lh.y = (ab - cd) * S;
            hl.y = (amb + cmd) * S; hh.y = (amb - cmd) * S;
        }
        {
            float ab = r0b.x + r0b.y, cd = r1b.x + r1b.y;
            float amb = r0b.x - r0b.y, cmd = r1b.x - r1b.y;
            ll.z = (ab + cd) * S; lh.z = (ab - cd) * S;
            hl.z = (amb + cmd) * S; hh.z = (amb - cmd) * S;
        }
        {
            float ab = r0b.z + r0b.w, cd = r1b.z + r1b.w;
            float amb = r0b.z - r0b.w, cmd = r1b.z - r1b.w;
            ll.w = (ab + cd) * S; lh.w = (ab - cd) * S;
            hl.w = (amb + cmd) * S; hh.w = (amb - cmd) * S;
        }
        __stcs(reinterpret_cast<float4*>(out + obase), ll);
        __stcs(reinterpret_cast<float4*>(out + obase + (size_t)SUBBAND), lh);
        __stcs(reinterpret_cast<float4*>(out + obase + (size_t)SUBBAND*2), hl);
        __stcs(reinterpret_cast<float4*>(out + obase + (size_t)SUBBAND*3), hh);
    }

    // ---- output row 1 (input rows 2,3) ----
    {
        size_t obase1 = obase + OUT_W;
        float4 ll, lh, hl, hh;
        {
            float ab = r2a.x + r2a.y, cd = r3a.x + r3a.y;
            float amb = r2a.x - r2a.y, cmd = r3a.x - r3a.y;
            ll.x = (ab + cd) * S; lh.x = (ab - cd) * S;
            hl.x = (amb + cmd) * S; hh.x = (amb - cmd) * S;
        }
        {
            float ab = r2a.z + r2a.w, cd = r3a.z + r3a.w;
            float amb = r2a.z - r2a.w, cmd = r3a.z - r3a.w;
            ll.y = (ab + cd) * S; lh.y = (ab - cd) * S;
            hl.y = (amb + cmd) * S; hh.y = (amb - cmd) * S;
        }
        {
            float ab = r2b.x + r2b.y, cd = r3b.x + r3b.y;
            float amb = r2b.x - r2b.y, cmd = r3b.x - r3b.y;
            ll.z = (ab + cd) * S; lh.z = (ab - cd) * S;
            hl.z = (amb + cmd) * S; hh.z = (amb - cmd) * S;
        }
        {
            float ab = r2b.z + r2b.w, cd = r3b.z + r3b.w;
            float amb = r2b.z - r2b.w, cmd = r3b.z - r3b.w;
            ll.w = (ab + cd) * S; lh.w = (ab - cd) * S;
            hl.w = (amb + cmd) * S; hh.w = (amb - cmd) * S;
        }
        __stcs(reinterpret_cast<float4*>(out + obase1), ll);
        __stcs(reinterpret_cast<float4*>(out + obase1 + (size_t)SUBBAND), lh);
        __stcs(reinterpret_cast<float4*>(out + obase1 + (size_t)SUBBAND*2), hl);
        __stcs(reinterpret_cast<float4*>(out + obase1 + (size_t)SUBBAND*3), hh);
    }
}

extern "C" void kernel_launch(void* const* d_in, const int* in_sizes, int n_in,
                              void* d_out, int out_size)
{
    const float* x = (const float*)d_in[0];
    float* out = (float*)d_out;
    // 4,194,304 threads / 256 = 16384 blocks
    haar_dwt2_kernel<<<16384, 256>>>(x, out);
}